// round 7
// baseline (speedup 1.0000x reference)
#include <cuda_runtime.h>
#include <math.h>

typedef unsigned long long ull;

#define BB   64
#define DECL 12
#define FF   32
#define HH   512
#define EE   96
#define TT   4
#define G3   1536
#define NPRE 3584   /* 512 (query) + 1536 (gh0) + 1536 (gh1) */
#define KX0  544    /* F + H */
#define KOUT 1056   /* 2H + F */
#define NBLK 148
#define NHALF 296

// ---------------- device scratch ----------------
__device__ __align__(16) float g_encproj[BB*EE*HH];   // 12.6 MB
__device__ __align__(16) float g_h0[BB*HH];
__device__ __align__(16) float g_h1[BB*HH];
__device__ __align__(16) float g_cur[BB*FF];
__device__ __align__(16) float g_pre[4][BB*NPRE];     // K-split x4 partials: query|gh0|gh1
__device__ __align__(16) float g_gi[8][BB*G3];        // K-split x8 partials for gi
__device__ __align__(16) float g_x0[BB*KX0];          // [cur | ws]
__device__ __align__(16) float g_ws[BB*HH];
__device__ __align__(16) float g_sc[BB*EE];           // attention scores

__device__ volatile unsigned g_arrive = 0;   // monotonic across replays
__device__ volatile unsigned g_gen    = 0;   // monotonic across replays

// ---------------- shared (two halves, aliased across phases) ----------------
__shared__ __align__(16) float sA[2][32*132];   // GEMM A (dup-pair, k-major) / qs,vs / ho
__shared__ __align__(16) float sW[2][32*66];    // GEMM W (k-major) / sc / red

// ---------------- helpers ----------------
__device__ __forceinline__ float fast_sigmoid(float x) {
    return 1.0f / (1.0f + __expf(-x));
}
__device__ __forceinline__ float fast_tanh(float x) {
    float e = __expf(-2.0f * fabsf(x));
    float t = (1.0f - e) / (1.0f + e);
    return copysignf(t, x);
}
__device__ __forceinline__ ull pack2(float x) {
    ull r;
    asm("mov.b64 %0, {%1, %1};" : "=l"(r) : "f"(x));
    return r;
}
__device__ __forceinline__ void ffma2(ull &d, ull a, ull b) {
    asm("fma.rn.f32x2 %0, %1, %2, %0;" : "+l"(d) : "l"(a), "l"(b));
}
__device__ __forceinline__ float2 unpack2(ull v) {
    float2 r;
    asm("mov.b64 {%0, %1}, %2;" : "=f"(r.x), "=f"(r.y) : "l"(v));
    return r;
}
// half-block barrier (256 threads), ids 1/2
__device__ __forceinline__ void hbar(int half) {
    asm volatile("bar.sync %0, 256;" :: "r"(half + 1) : "memory");
}

// grid barrier: REDG arrivals + block0 monitor, monotonic generation (replay-safe)
__device__ __forceinline__ void gsync(unsigned &nbar) {
    __syncthreads();
    if (threadIdx.x == 0) {
        __threadfence();
        atomicAdd((unsigned*)&g_arrive, 1u);       // return unused -> RED
        if (blockIdx.x == 0) {
            while (g_arrive < (nbar + 1u) * NBLK) { }
            __threadfence();
            g_gen = nbar + 1u;
        } else {
            while (g_gen < nbar + 1u) { }
        }
        __threadfence();
    }
    nbar++;
    __syncthreads();
}

// ---------------- half-block f32x2 GEMM: C[64][64] = A[64][klen] @ W[64][klen]^T ----
// 256 threads (one half). klen % 32 == 0. A/W/C pre-offset to tile origin.
template<bool ACG>
__device__ __forceinline__ void gemm64(
    int half, int htid,
    const float* __restrict__ A, int lda,
    const float* __restrict__ W, int ldw,
    float* __restrict__ C, int ldc, int klen)
{
    const int warp_l = htid >> 5;
    const int lane   = htid & 31;
    float* As = sA[half];
    float* Ws = sW[half];
    ull acc[8] = {};

    for (int k0 = 0; k0 < klen; k0 += 32) {
        #pragma unroll
        for (int ph = 0; ph < 2; ph++) {
            int t   = htid + ph * 256;
            int row = t >> 3;
            int q   = (t & 7) << 2;
            const float4* pa = reinterpret_cast<const float4*>(&A[row*lda + k0 + q]);
            float4 va = ACG ? __ldcg(pa) : __ldg(pa);
            // A: dup-pair, k-major: As[kk][2*row..2*row+1] = {a,a}
            *reinterpret_cast<ull*>(&As[(q+0)*132 + 2*row]) = pack2(va.x);
            *reinterpret_cast<ull*>(&As[(q+1)*132 + 2*row]) = pack2(va.y);
            *reinterpret_cast<ull*>(&As[(q+2)*132 + 2*row]) = pack2(va.z);
            *reinterpret_cast<ull*>(&As[(q+3)*132 + 2*row]) = pack2(va.w);
            float4 vw = __ldg(reinterpret_cast<const float4*>(&W[row*ldw + k0 + q]));
            Ws[(q+0)*66 + row] = vw.x;
            Ws[(q+1)*66 + row] = vw.y;
            Ws[(q+2)*66 + row] = vw.z;
            Ws[(q+3)*66 + row] = vw.w;
        }
        hbar(half);

        #pragma unroll
        for (int kk = 0; kk < 32; kk++) {
            ull w = *reinterpret_cast<const ull*>(&Ws[kk*66 + 2*lane]);
            const ulonglong2* ap =
                reinterpret_cast<const ulonglong2*>(&As[kk*132 + 16*warp_l]);
            ulonglong2 p0 = ap[0];   // rows +0,+1 (broadcast)
            ulonglong2 p1 = ap[1];   // rows +2,+3
            ulonglong2 p2 = ap[2];   // rows +4,+5
            ulonglong2 p3 = ap[3];   // rows +6,+7
            ffma2(acc[0], p0.x, w); ffma2(acc[1], p0.y, w);
            ffma2(acc[2], p1.x, w); ffma2(acc[3], p1.y, w);
            ffma2(acc[4], p2.x, w); ffma2(acc[5], p2.y, w);
            ffma2(acc[6], p3.x, w); ffma2(acc[7], p3.y, w);
        }
        hbar(half);
    }

    const int c2 = 2 * lane;
    #pragma unroll
    for (int r = 0; r < 8; r++) {
        int row = warp_l * 8 + r;
        __stcg(reinterpret_cast<float2*>(&C[row*ldc + c2]), unpack2(acc[r]));
    }
}

// ---------------- the whole decoder, persistent ----------------
__global__ __launch_bounds__(512, 1) void k_decoder(
    const float* __restrict__ inputs, const float* __restrict__ hidden,
    const float* __restrict__ enc,    const int* __restrict__ tind,
    const float* __restrict__ Wattn,  const float* __restrict__ b_attn,
    const float* __restrict__ v_attn,
    const float* __restrict__ Wi0, const float* __restrict__ Wh0,
    const float* __restrict__ bi0, const float* __restrict__ bh0,
    const float* __restrict__ Wi1, const float* __restrict__ Wh1,
    const float* __restrict__ bi1, const float* __restrict__ bh1,
    const float* __restrict__ W_out, const float* __restrict__ b_out,
    float* __restrict__ dout)
{
    const int bid    = blockIdx.x;
    const int tid    = threadIdx.x;
    const int half   = tid >> 8;         // 0/1
    const int htid   = tid & 255;
    const int warp_l = htid >> 5;        // 0..7
    const int lane   = tid & 31;
    const int hb     = bid * 2 + half;   // virtual CTA id, 0..295

    unsigned nbar = g_gen;               // monotonic base (replay-safe)

    // ===== init copies =====
    for (int i = bid*512 + tid; i < BB*HH; i += NBLK*512) {
        __stcg(&g_h0[i], __ldg(&hidden[i]));
        __stcg(&g_h1[i], __ldg(&hidden[BB*HH + i]));
    }
    for (int i = bid*512 + tid; i < BB*FF; i += NBLK*512) {
        int b = i >> 5, f = i & 31;
        __stcg(&g_cur[i], __ldg(&inputs[b*DECL*FF + f]));
    }

    // ===== phase E: enc_proj  (96 M-tiles x 8 N-tiles, K=512) =====
    for (int it = hb; it < 96*8; it += NHALF) {
        int m = it >> 3, n = it & 7;
        gemm64<false>(half, htid,
                      enc + m*64*HH, HH,
                      Wattn + n*64*(2*HH) + HH, 2*HH,
                      g_encproj + m*64*HH + n*64, HH, HH);
    }
    gsync(nbar);

    // ===== 12 decode steps =====
    for (int t = 0; t < DECL; t++) {
        // --- P1: pre GEMM (query | gh0 | gh1): 56 N-tiles(64) x Ksplit4(128) = 224 jobs
        for (int it = hb; it < 224; it += NHALF) {
            int col0 = (it >> 2) * 64;
            int s    = it & 3;
            int k0   = s * 128;
            const float* A; const float* W; int ldw;
            if (col0 < 512)       { A = g_h1; W = Wattn + col0*(2*HH);   ldw = 2*HH; }
            else if (col0 < 2048) { A = g_h0; W = Wh0 + (col0-512)*HH;   ldw = HH; }
            else                  { A = g_h1; W = Wh1 + (col0-2048)*HH;  ldw = HH; }
            gemm64<true>(half, htid, A + k0, HH, W + k0, ldw,
                         g_pre[s] + col0, NPRE, 128);
        }
        gsync(nbar);

        // --- P2: scores: job = (b, part12), 8 energies each; 768 jobs
        for (int it = hb; it < BB*12; it += NHALF) {
            hbar(half);
            int b = it / 12, part = it % 12;
            float* qs = sA[half];
            float* vs = sA[half] + 512;
            for (int i = htid; i < HH; i += 256) {
                float q = __ldg(&b_attn[i]);
                #pragma unroll
                for (int s = 0; s < 4; s++) q += __ldcg(&g_pre[s][b*NPRE + i]);
                qs[i] = q;
                vs[i] = __ldg(&v_attn[i]);
            }
            hbar(half);
            int e = part*8 + warp_l;
            const float4* ep4 = reinterpret_cast<const float4*>(g_encproj + (b*EE + e)*HH);
            float ssum = 0.0f;
            #pragma unroll
            for (int i = 0; i < 4; i++) {
                float4 v = __ldg(&ep4[i*32 + lane]);
                int g = (i*32 + lane) * 4;
                ssum += fast_tanh(v.x + qs[g  ]) * vs[g  ];
                ssum += fast_tanh(v.y + qs[g+1]) * vs[g+1];
                ssum += fast_tanh(v.z + qs[g+2]) * vs[g+2];
                ssum += fast_tanh(v.w + qs[g+3]) * vs[g+3];
            }
            #pragma unroll
            for (int off = 16; off > 0; off >>= 1)
                ssum += __shfl_xor_sync(0xffffffffu, ssum, off);
            if (lane == 0) __stcg(&g_sc[b*EE + e], ssum);
        }
        gsync(nbar);

        // --- P3: softmax + ws + assemble x0 : job = (b, col-half); 128 jobs
        for (int it = hb; it < BB*2; it += NHALF) {
            int b = it >> 1, jh = it & 1;
            float* sc = sW[half];
            if (htid < 32) {
                float s0 = __ldcg(&g_sc[b*EE + htid]);
                float s1 = __ldcg(&g_sc[b*EE + htid + 32]);
                float s2 = __ldcg(&g_sc[b*EE + htid + 64]);
                float m = fmaxf(s0, fmaxf(s1, s2));
                #pragma unroll
                for (int off = 16; off > 0; off >>= 1)
                    m = fmaxf(m, __shfl_xor_sync(0xffffffffu, m, off));
                float p0 = __expf(s0-m), p1 = __expf(s1-m), p2 = __expf(s2-m);
                float sum = p0 + p1 + p2;
                #pragma unroll
                for (int off = 16; off > 0; off >>= 1)
                    sum += __shfl_xor_sync(0xffffffffu, sum, off);
                float inv = 1.0f / sum;
                sc[htid] = p0*inv; sc[htid+32] = p1*inv; sc[htid+64] = p2*inv;
            }
            hbar(half);
            int col = jh*256 + htid;
            float acc = 0.0f;
            const float* eb = enc + b*EE*HH + col;
            #pragma unroll 8
            for (int e = 0; e < EE; e++) acc += sc[e] * __ldg(&eb[e*HH]);
            __stcg(&g_ws[b*HH + col], acc);
            __stcg(&g_x0[b*KX0 + FF + col], acc);
            if (jh == 0 && htid < FF)
                __stcg(&g_x0[b*KX0 + htid], __ldcg(&g_cur[b*FF + htid]));
        }
        gsync(nbar);

        // --- P4: gi0 = x0 @ Wi0^T : 24 N-tiles(64) x Ksplit8 {96,64x7} = 192 jobs
        for (int it = hb; it < 192; it += NHALF) {
            int col0 = (it >> 3) * 64;
            int s    = it & 7;
            int k0   = (s == 0) ? 0 : (32 + s*64);
            int klen = (s == 0) ? 96 : 64;
            gemm64<true>(half, htid, g_x0 + k0, KX0, Wi0 + col0*KX0 + k0, KX0,
                         g_gi[s] + col0, G3, klen);
        }
        gsync(nbar);

        // --- P5: GRU combine layer 0 -> h0 : 128 jobs (b, j-half)
        for (int it = hb; it < BB*2; it += NHALF) {
            int b = it >> 1;
            int j = (it & 1)*256 + htid;
            float ir = __ldg(&bi0[j]), iz = __ldg(&bi0[j+HH]), in_ = __ldg(&bi0[j+2*HH]);
            float hr = __ldg(&bh0[j]), hz = __ldg(&bh0[j+HH]), hn  = __ldg(&bh0[j+2*HH]);
            #pragma unroll
            for (int s = 0; s < 8; s++) {
                const float* gi = g_gi[s] + b*G3;
                ir += __ldcg(&gi[j]); iz += __ldcg(&gi[j+HH]); in_ += __ldcg(&gi[j+2*HH]);
            }
            #pragma unroll
            for (int s = 0; s < 4; s++) {
                const float* gh = g_pre[s] + b*NPRE + 512;
                hr += __ldcg(&gh[j]); hz += __ldcg(&gh[j+HH]); hn += __ldcg(&gh[j+2*HH]);
            }
            float r = fast_sigmoid(ir + hr);
            float z = fast_sigmoid(iz + hz);
            float n = fast_tanh(in_ + r * hn);
            float hp = __ldcg(&g_h0[b*HH + j]);
            __stcg(&g_h0[b*HH + j], (1.0f - z)*n + z*hp);
        }
        gsync(nbar);

        // --- P6: gi1 = h0_new @ Wi1^T : 24 N-tiles(64) x Ksplit8(64) = 192 jobs
        for (int it = hb; it < 192; it += NHALF) {
            int col0 = (it >> 3) * 64;
            int s    = it & 7;
            int k0   = s * 64;
            gemm64<true>(half, htid, g_h0 + k0, HH, Wi1 + col0*HH + k0, HH,
                         g_gi[s] + col0, G3, 64);
        }
        gsync(nbar);

        // --- P7: GRU combine layer 1 -> h1, fused out-proj + next cur : 64 jobs
        for (int it = hb; it < BB; it += NHALF) {
            int b = it;
            float* ho  = sA[half];       // 512 floats
            float* red = sW[half];       // 32 + 4
            #pragma unroll
            for (int jj = 0; jj < 2; jj++) {
                int j = jj*256 + htid;
                float ir = __ldg(&bi1[j]), iz = __ldg(&bi1[j+HH]), in_ = __ldg(&bi1[j+2*HH]);
                float hr = __ldg(&bh1[j]), hz = __ldg(&bh1[j+HH]), hn  = __ldg(&bh1[j+2*HH]);
                #pragma unroll
                for (int s = 0; s < 8; s++) {
                    const float* gi = g_gi[s] + b*G3;
                    ir += __ldcg(&gi[j]); iz += __ldcg(&gi[j+HH]); in_ += __ldcg(&gi[j+2*HH]);
                }
                #pragma unroll
                for (int s = 0; s < 4; s++) {
                    const float* gh = g_pre[s] + b*NPRE + 2048;
                    hr += __ldcg(&gh[j]); hz += __ldcg(&gh[j+HH]); hn += __ldcg(&gh[j+2*HH]);
                }
                float r = fast_sigmoid(ir + hr);
                float z = fast_sigmoid(iz + hz);
                float n = fast_tanh(in_ + r * hn);
                float hp = __ldcg(&g_h1[b*HH + j]);
                float h1n = (1.0f - z)*n + z*hp;
                __stcg(&g_h1[b*HH + j], h1n);
                ho[j] = h1n;
            }
            hbar(half);

            float a0 = 0.f, a1 = 0.f, a2 = 0.f, a3 = 0.f;
            for (int k = htid; k < KOUT; k += 256) {
                float x;
                if (k < HH)          x = ho[k];
                else if (k < 2*HH)   x = __ldcg(&g_ws[b*HH + k - HH]);
                else                 x = __ldcg(&g_cur[b*FF + (k - 2*HH)]);
                a0 += x * __ldg(&W_out[k]);
                a1 += x * __ldg(&W_out[KOUT + k]);
                a2 += x * __ldg(&W_out[2*KOUT + k]);
                a3 += x * __ldg(&W_out[3*KOUT + k]);
            }
            #pragma unroll
            for (int off = 16; off > 0; off >>= 1) {
                a0 += __shfl_xor_sync(0xffffffffu, a0, off);
                a1 += __shfl_xor_sync(0xffffffffu, a1, off);
                a2 += __shfl_xor_sync(0xffffffffu, a2, off);
                a3 += __shfl_xor_sync(0xffffffffu, a3, off);
            }
            if (lane == 0) {
                red[0*8 + warp_l] = a0; red[1*8 + warp_l] = a1;
                red[2*8 + warp_l] = a2; red[3*8 + warp_l] = a3;
            }
            hbar(half);
            if (htid < 4) {
                float s = __ldg(&b_out[htid]);
                #pragma unroll
                for (int w = 0; w < 8; w++) s += red[htid*8 + w];
                dout[(b*DECL + t)*TT + htid] = s;
                red[32 + htid] = s;
            }
            hbar(half);
            if (htid < FF)
                __stcg(&g_cur[b*FF + htid], __ldg(&inputs[(b*DECL + t)*FF + htid]));
            hbar(half);
            if (htid < TT)
                __stcg(&g_cur[b*FF + __ldg(&tind[htid])], red[32 + htid]);
        }
        if (t < DECL - 1) gsync(nbar);
    }
}

// ---------------- launch ----------------
extern "C" void kernel_launch(void* const* d_in, const int* in_sizes, int n_in,
                              void* d_out, int out_size)
{
    const float* inputs   = (const float*)d_in[0];
    const float* hidden   = (const float*)d_in[1];
    const float* enc      = (const float*)d_in[2];
    const int*   tindices = (const int*)  d_in[3];
    const float* W_attn   = (const float*)d_in[4];
    const float* b_attn   = (const float*)d_in[5];
    const float* v_attn   = (const float*)d_in[6];
    const float* Wi0      = (const float*)d_in[7];
    const float* Wh0      = (const float*)d_in[8];
    const float* bi0      = (const float*)d_in[9];
    const float* bh0      = (const float*)d_in[10];
    const float* Wi1      = (const float*)d_in[11];
    const float* Wh1      = (const float*)d_in[12];
    const float* bi1      = (const float*)d_in[13];
    const float* bh1      = (const float*)d_in[14];
    const float* W_out    = (const float*)d_in[15];
    const float* b_out    = (const float*)d_in[16];
    float* out = (float*)d_out;

    k_decoder<<<NBLK, 512>>>(inputs, hidden, enc, tindices,
                             W_attn, b_attn, v_attn,
                             Wi0, Wh0, bi0, bh0,
                             Wi1, Wh1, bi1, bh1,
                             W_out, b_out, out);
}

// round 8
// speedup vs baseline: 1.5845x; 1.5845x over previous
#include <cuda_runtime.h>
#include <cuda_bf16.h>
#include <math.h>

typedef unsigned int uint;

#define BB   64
#define DECL 12
#define FF   32
#define HH   512
#define EE   96
#define TT   4
#define G3   1536
#define NPRE 3584   /* 512 (query) + 1536 (gh0) + 1536 (gh1) */
#define KX0  544    /* F + H */
#define KOUT 1056   /* 2H + F */
#define NBLK 148
#define SR   40     /* smem bf16 plane row stride (conflict-free) */

// ---------------- device scratch ----------------
__device__ __align__(16) float g_encproj[BB*EE*HH];   // 12.6 MB
__device__ __align__(16) float g_h0[BB*HH];
__device__ __align__(16) float g_h1[BB*HH];
__device__ __align__(16) float g_cur[BB*FF];
__device__ __align__(16) float g_pre[8][BB*NPRE];     // K-split x8 partials: query|gh0|gh1
__device__ __align__(16) float g_gi[8][BB*G3];        // K-split x8 partials for gi
__device__ __align__(16) float g_x0[BB*KX0];          // [cur | ws]
__device__ __align__(16) float g_ws[BB*HH];
__device__ __align__(16) float g_sc[BB*EE];           // attention scores

__device__ unsigned g_bar_cnt = 0;
__device__ unsigned g_bar_gen = 0;

// ---------------- shared ----------------
__shared__ __align__(16) __nv_bfloat16 sAH[64*SR];   // A hi plane
__shared__ __align__(16) __nv_bfloat16 sAL[64*SR];   // A lo plane
__shared__ __align__(16) __nv_bfloat16 sWH[64*SR];   // W hi plane
__shared__ __align__(16) __nv_bfloat16 sWL[64*SR];   // W lo plane
__shared__ __align__(16) float sBuf[1100];           // qs|vs / sc / ho|red

// ---------------- helpers ----------------
__device__ __forceinline__ float fast_sigmoid(float x) {
    return 1.0f / (1.0f + __expf(-x));
}
__device__ __forceinline__ float fast_tanh(float x) {
    float e = __expf(-2.0f * fabsf(x));
    float t = (1.0f - e) / (1.0f + e);
    return copysignf(t, x);
}

// split two fp32 into packed bf16 hi pair (ret) and lo pair (out param)
__device__ __forceinline__ uint splitpack(float x, float y, uint &lo) {
    __nv_bfloat16 hx = __float2bfloat16(x);
    __nv_bfloat16 hy = __float2bfloat16(y);
    __nv_bfloat16 lx = __float2bfloat16(x - __bfloat162float(hx));
    __nv_bfloat16 ly = __float2bfloat16(y - __bfloat162float(hy));
    lo = ((uint)__bfloat16_as_ushort(ly) << 16) | (uint)__bfloat16_as_ushort(lx);
    return ((uint)__bfloat16_as_ushort(hy) << 16) | (uint)__bfloat16_as_ushort(hx);
}

__device__ __forceinline__ uint lds32(const __nv_bfloat16* p, int r, int c) {
    return *reinterpret_cast<const uint*>(&p[r*SR + c]);
}

__device__ __forceinline__ void mma16816(float* d, const uint* a, uint b0, uint b1) {
    asm volatile(
        "mma.sync.aligned.m16n8k16.row.col.f32.bf16.bf16.f32 "
        "{%0,%1,%2,%3},{%4,%5,%6,%7},{%8,%9},{%0,%1,%2,%3};"
        : "+f"(d[0]), "+f"(d[1]), "+f"(d[2]), "+f"(d[3])
        : "r"(a[0]), "r"(a[1]), "r"(a[2]), "r"(a[3]), "r"(b0), "r"(b1));
}

// grid barrier (R6 version — proven)
__device__ __forceinline__ void gsync() {
    __syncthreads();
    if (threadIdx.x == 0) {
        __threadfence();
        unsigned gen = *((volatile unsigned*)&g_bar_gen);
        if (atomicAdd(&g_bar_cnt, 1u) == (unsigned)(NBLK - 1)) {
            g_bar_cnt = 0;
            __threadfence();
            *((volatile unsigned*)&g_bar_gen) = gen + 1u;
        } else {
            while (*((volatile unsigned*)&g_bar_gen) == gen) { }
        }
    }
    __syncthreads();
}

// ---------------- bf16x3 tensor-core GEMM: C[64][64] = A[64][klen] @ W[64][klen]^T
// 512 threads. klen % 32 == 0. A/W/C pre-offset to tile origin.
template<bool ACG>
__device__ __forceinline__ void gemm64t(
    const float* __restrict__ A, int lda,
    const float* __restrict__ W, int ldw,
    float* __restrict__ C, int ldc, int klen)
{
    const int tid  = threadIdx.x;
    const int warp = tid >> 5, lane = tid & 31;
    const int rt = warp >> 2, ct = warp & 3;      // warp tile: rows rt*16, cols ct*16
    const int g  = lane >> 2;                     // 0..7
    const int q  = (lane & 3) << 1;               // 0,2,4,6
    const int srow = tid >> 3, sq = (tid & 7) << 2;
    float d[2][4] = {};

    const float4* pa = reinterpret_cast<const float4*>(&A[srow*lda + sq]);
    const float4* pw = reinterpret_cast<const float4*>(&W[srow*ldw + sq]);
    float4 va = ACG ? __ldcg(pa) : __ldg(pa);
    float4 vw = __ldg(pw);

    for (int k0 = 0; k0 < klen; k0 += 32) {
        // stage current chunk (fp32 -> bf16 hi/lo planes)
        uint l01, l23;
        uint h01 = splitpack(va.x, va.y, l01);
        uint h23 = splitpack(va.z, va.w, l23);
        *reinterpret_cast<uint*>(&sAH[srow*SR + sq])     = h01;
        *reinterpret_cast<uint*>(&sAH[srow*SR + sq + 2]) = h23;
        *reinterpret_cast<uint*>(&sAL[srow*SR + sq])     = l01;
        *reinterpret_cast<uint*>(&sAL[srow*SR + sq + 2]) = l23;
        h01 = splitpack(vw.x, vw.y, l01);
        h23 = splitpack(vw.z, vw.w, l23);
        *reinterpret_cast<uint*>(&sWH[srow*SR + sq])     = h01;
        *reinterpret_cast<uint*>(&sWH[srow*SR + sq + 2]) = h23;
        *reinterpret_cast<uint*>(&sWL[srow*SR + sq])     = l01;
        *reinterpret_cast<uint*>(&sWL[srow*SR + sq + 2]) = l23;
        __syncthreads();

        // prefetch next chunk (overlaps MMA below)
        if (k0 + 32 < klen) {
            pa = reinterpret_cast<const float4*>(&A[srow*lda + k0 + 32 + sq]);
            pw = reinterpret_cast<const float4*>(&W[srow*ldw + k0 + 32 + sq]);
            va = ACG ? __ldcg(pa) : __ldg(pa);
            vw = __ldg(pw);
        }

        #pragma unroll
        for (int ks = 0; ks < 32; ks += 16) {
            uint aH[4], aL[4];
            const int r0 = rt*16 + g;
            aH[0] = lds32(sAH, r0,     ks+q);   aH[1] = lds32(sAH, r0 + 8, ks+q);
            aH[2] = lds32(sAH, r0,     ks+q+8); aH[3] = lds32(sAH, r0 + 8, ks+q+8);
            aL[0] = lds32(sAL, r0,     ks+q);   aL[1] = lds32(sAL, r0 + 8, ks+q);
            aL[2] = lds32(sAL, r0,     ks+q+8); aL[3] = lds32(sAL, r0 + 8, ks+q+8);
            #pragma unroll
            for (int nt = 0; nt < 2; nt++) {
                const int n0 = ct*16 + nt*8 + g;
                uint bH0 = lds32(sWH, n0, ks+q), bH1 = lds32(sWH, n0, ks+q+8);
                uint bL0 = lds32(sWL, n0, ks+q), bL1 = lds32(sWL, n0, ks+q+8);
                mma16816(d[nt], aH, bH0, bH1);   // hi*hi
                mma16816(d[nt], aH, bL0, bL1);   // hi*lo
                mma16816(d[nt], aL, bH0, bH1);   // lo*hi
            }
        }
        __syncthreads();
    }

    const int r0 = rt*16 + g;
    #pragma unroll
    for (int nt = 0; nt < 2; nt++) {
        const int c0 = ct*16 + nt*8 + q;
        __stcg(reinterpret_cast<float2*>(&C[r0*ldc + c0]),       make_float2(d[nt][0], d[nt][1]));
        __stcg(reinterpret_cast<float2*>(&C[(r0 + 8)*ldc + c0]), make_float2(d[nt][2], d[nt][3]));
    }
}

// ---------------- the whole decoder, persistent ----------------
__global__ __launch_bounds__(512, 1) void k_decoder(
    const float* __restrict__ inputs, const float* __restrict__ hidden,
    const float* __restrict__ enc,    const int* __restrict__ tind,
    const float* __restrict__ Wattn,  const float* __restrict__ b_attn,
    const float* __restrict__ v_attn,
    const float* __restrict__ Wi0, const float* __restrict__ Wh0,
    const float* __restrict__ bi0, const float* __restrict__ bh0,
    const float* __restrict__ Wi1, const float* __restrict__ Wh1,
    const float* __restrict__ bi1, const float* __restrict__ bh1,
    const float* __restrict__ W_out, const float* __restrict__ b_out,
    float* __restrict__ dout)
{
    const int bid  = blockIdx.x;
    const int tid  = threadIdx.x;
    const int warp = tid >> 5, lane = tid & 31;

    // ===== init copies =====
    for (int i = bid*512 + tid; i < BB*HH; i += NBLK*512) {
        __stcg(&g_h0[i], __ldg(&hidden[i]));
        __stcg(&g_h1[i], __ldg(&hidden[BB*HH + i]));
    }
    for (int i = bid*512 + tid; i < BB*FF; i += NBLK*512) {
        int b = i >> 5, f = i & 31;
        __stcg(&g_cur[i], __ldg(&inputs[b*DECL*FF + f]));
    }

    // ===== phase E: enc_proj (96 M-tiles x 8 N-tiles, K=512) =====
    for (int it = bid; it < 96*8; it += NBLK) {
        int m = it >> 3, n = it & 7;
        gemm64t<false>(enc + m*64*HH, HH,
                       Wattn + n*64*(2*HH) + HH, 2*HH,
                       g_encproj + m*64*HH + n*64, HH, HH);
    }
    gsync();

    // ===== 12 decode steps =====
    for (int t = 0; t < DECL; t++) {
        // --- P1: pre GEMM (query|gh0|gh1): 56 N-tiles(64) x Ksplit8(64) = 448 jobs
        for (int it = bid; it < 448; it += NBLK) {
            int col0 = (it >> 3) * 64;
            int s    = it & 7;
            int k0   = s * 64;
            const float* A; const float* W; int ldw;
            if (col0 < 512)       { A = g_h1; W = Wattn + col0*(2*HH);   ldw = 2*HH; }
            else if (col0 < 2048) { A = g_h0; W = Wh0 + (col0-512)*HH;   ldw = HH; }
            else                  { A = g_h1; W = Wh1 + (col0-2048)*HH;  ldw = HH; }
            gemm64t<true>(A + k0, HH, W + k0, ldw, g_pre[s] + col0, NPRE, 64);
        }
        gsync();

        // --- P2: scores: job = (b, part), 16 energies; 384 jobs
        for (int it = bid; it < BB*6; it += NBLK) {
            __syncthreads();
            int b = it / 6, part = it % 6;
            float* qs = sBuf;
            float* vs = sBuf + 512;
            float qv = __ldg(&b_attn[tid]);
            #pragma unroll
            for (int s = 0; s < 8; s++) qv += __ldcg(&g_pre[s][b*NPRE + tid]);
            qs[tid] = qv;
            vs[tid] = __ldg(&v_attn[tid]);
            __syncthreads();
            int e = part*16 + warp;
            const float4* ep4 = reinterpret_cast<const float4*>(g_encproj + (b*EE + e)*HH);
            float ssum = 0.0f;
            #pragma unroll
            for (int i = 0; i < 4; i++) {
                float4 v = __ldg(&ep4[i*32 + lane]);
                int gg = (i*32 + lane) * 4;
                ssum += fast_tanh(v.x + qs[gg  ]) * vs[gg  ];
                ssum += fast_tanh(v.y + qs[gg+1]) * vs[gg+1];
                ssum += fast_tanh(v.z + qs[gg+2]) * vs[gg+2];
                ssum += fast_tanh(v.w + qs[gg+3]) * vs[gg+3];
            }
            #pragma unroll
            for (int off = 16; off > 0; off >>= 1)
                ssum += __shfl_xor_sync(0xffffffffu, ssum, off);
            if (lane == 0) __stcg(&g_sc[b*EE + e], ssum);
        }
        gsync();

        // --- P3: softmax + ws + assemble x0 : 64 jobs
        for (int it = bid; it < BB; it += NBLK) {
            __syncthreads();
            int b = it;
            float* sc = sBuf;
            if (warp == 0) {
                float s0 = __ldcg(&g_sc[b*EE + lane]);
                float s1 = __ldcg(&g_sc[b*EE + lane + 32]);
                float s2 = __ldcg(&g_sc[b*EE + lane + 64]);
                float m = fmaxf(s0, fmaxf(s1, s2));
                #pragma unroll
                for (int off = 16; off > 0; off >>= 1)
                    m = fmaxf(m, __shfl_xor_sync(0xffffffffu, m, off));
                float p0 = __expf(s0-m), p1 = __expf(s1-m), p2 = __expf(s2-m);
                float sum = p0 + p1 + p2;
                #pragma unroll
                for (int off = 16; off > 0; off >>= 1)
                    sum += __shfl_xor_sync(0xffffffffu, sum, off);
                float inv = 1.0f / sum;
                sc[lane] = p0*inv; sc[lane+32] = p1*inv; sc[lane+64] = p2*inv;
            }
            __syncthreads();
            float acc = 0.0f;
            const float* eb = enc + b*EE*HH + tid;
            #pragma unroll 8
            for (int e = 0; e < EE; e++) acc += sc[e] * __ldg(&eb[e*HH]);
            __stcg(&g_ws[b*HH + tid], acc);
            __stcg(&g_x0[b*KX0 + FF + tid], acc);
            if (tid < FF) __stcg(&g_x0[b*KX0 + tid], __ldcg(&g_cur[b*FF + tid]));
        }
        gsync();

        // --- P4: gi0 = x0 @ Wi0^T : 24 N-tiles(64) x Ksplit8 {96,64x7} = 192 jobs
        for (int it = bid; it < 192; it += NBLK) {
            int col0 = (it >> 3) * 64;
            int s    = it & 7;
            int k0   = (s == 0) ? 0 : (32 + s*64);
            int klen = (s == 0) ? 96 : 64;
            gemm64t<true>(g_x0 + k0, KX0, Wi0 + col0*KX0 + k0, KX0,
                          g_gi[s] + col0, G3, klen);
        }
        gsync();

        // --- P5: GRU combine layer 0 -> h0 : 64 jobs
        for (int it = bid; it < BB; it += NBLK) {
            int b = it, j = tid;
            float ir = __ldg(&bi0[j]), iz = __ldg(&bi0[j+HH]), in_ = __ldg(&bi0[j+2*HH]);
            float hr = __ldg(&bh0[j]), hz = __ldg(&bh0[j+HH]), hn  = __ldg(&bh0[j+2*HH]);
            #pragma unroll
            for (int s = 0; s < 8; s++) {
                const float* gi = g_gi[s] + b*G3;
                ir += __ldcg(&gi[j]); iz += __ldcg(&gi[j+HH]); in_ += __ldcg(&gi[j+2*HH]);
                const float* gh = g_pre[s] + b*NPRE + 512;
                hr += __ldcg(&gh[j]); hz += __ldcg(&gh[j+HH]); hn += __ldcg(&gh[j+2*HH]);
            }
            float r = fast_sigmoid(ir + hr);
            float z = fast_sigmoid(iz + hz);
            float n = fast_tanh(in_ + r * hn);
            float hp = __ldcg(&g_h0[b*HH + j]);
            __stcg(&g_h0[b*HH + j], (1.0f - z)*n + z*hp);
        }
        gsync();

        // --- P6: gi1 = h0_new @ Wi1^T : 24 N-tiles(64) x Ksplit8(64) = 192 jobs
        for (int it = bid; it < 192; it += NBLK) {
            int col0 = (it >> 3) * 64;
            int s    = it & 7;
            int k0   = s * 64;
            gemm64t<true>(g_h0 + k0, HH, Wi1 + col0*HH + k0, HH,
                          g_gi[s] + col0, G3, 64);
        }
        gsync();

        // --- P7: GRU combine layer 1 -> h1, fused out-proj + next cur : 64 jobs
        for (int it = bid; it < BB; it += NBLK) {
            __syncthreads();
            int b = it, j = tid;
            float* ho  = sBuf;          // 512
            float* red = sBuf + 512;    // 64 + 4
            float ir = __ldg(&bi1[j]), iz = __ldg(&bi1[j+HH]), in_ = __ldg(&bi1[j+2*HH]);
            float hr = __ldg(&bh1[j]), hz = __ldg(&bh1[j+HH]), hn  = __ldg(&bh1[j+2*HH]);
            #pragma unroll
            for (int s = 0; s < 8; s++) {
                const float* gi = g_gi[s] + b*G3;
                ir += __ldcg(&gi[j]); iz += __ldcg(&gi[j+HH]); in_ += __ldcg(&gi[j+2*HH]);
                const float* gh = g_pre[s] + b*NPRE + 2048;
                hr += __ldcg(&gh[j]); hz += __ldcg(&gh[j+HH]); hn += __ldcg(&gh[j+2*HH]);
            }
            float r = fast_sigmoid(ir + hr);
            float z = fast_sigmoid(iz + hz);
            float n = fast_tanh(in_ + r * hn);
            float hp = __ldcg(&g_h1[b*HH + j]);
            float h1n = (1.0f - z)*n + z*hp;
            __stcg(&g_h1[b*HH + j], h1n);
            ho[j] = h1n;
            __syncthreads();

            float a0 = 0.f, a1 = 0.f, a2 = 0.f, a3 = 0.f;
            for (int k = tid; k < KOUT; k += 512) {
                float x;
                if (k < HH)          x = ho[k];
                else if (k < 2*HH)   x = __ldcg(&g_ws[b*HH + k - HH]);
                else                 x = __ldcg(&g_cur[b*FF + (k - 2*HH)]);
                a0 += x * __ldg(&W_out[k]);
                a1 += x * __ldg(&W_out[KOUT + k]);
                a2 += x * __ldg(&W_out[2*KOUT + k]);
                a3 += x * __ldg(&W_out[3*KOUT + k]);
            }
            #pragma unroll
            for (int off = 16; off > 0; off >>= 1) {
                a0 += __shfl_xor_sync(0xffffffffu, a0, off);
                a1 += __shfl_xor_sync(0xffffffffu, a1, off);
                a2 += __shfl_xor_sync(0xffffffffu, a2, off);
                a3 += __shfl_xor_sync(0xffffffffu, a3, off);
            }
            if (lane == 0) {
                red[0*16 + warp] = a0; red[1*16 + warp] = a1;
                red[2*16 + warp] = a2; red[3*16 + warp] = a3;
            }
            __syncthreads();
            if (tid < 4) {
                float s = __ldg(&b_out[tid]);
                #pragma unroll
                for (int w = 0; w < 16; w++) s += red[tid*16 + w];
                dout[(b*DECL + t)*TT + tid] = s;
                red[64 + tid] = s;
            }
            __syncthreads();
            if (tid < FF)
                __stcg(&g_cur[b*FF + tid], __ldg(&inputs[(b*DECL + t)*FF + tid]));
            __syncthreads();
            if (tid < TT)
                __stcg(&g_cur[b*FF + __ldg(&tind[tid])], red[64 + tid]);
        }
        if (t < DECL - 1) gsync();
    }
}

// ---------------- launch ----------------
extern "C" void kernel_launch(void* const* d_in, const int* in_sizes, int n_in,
                              void* d_out, int out_size)
{
    const float* inputs   = (const float*)d_in[0];
    const float* hidden   = (const float*)d_in[1];
    const float* enc      = (const float*)d_in[2];
    const int*   tindices = (const int*)  d_in[3];
    const float* W_attn   = (const float*)d_in[4];
    const float* b_attn   = (const float*)d_in[5];
    const float* v_attn   = (const float*)d_in[6];
    const float* Wi0      = (const float*)d_in[7];
    const float* Wh0      = (const float*)d_in[8];
    const float* bi0      = (const float*)d_in[9];
    const float* bh0      = (const float*)d_in[10];
    const float* Wi1      = (const float*)d_in[11];
    const float* Wh1      = (const float*)d_in[12];
    const float* bi1      = (const float*)d_in[13];
    const float* bh1      = (const float*)d_in[14];
    const float* W_out    = (const float*)d_in[15];
    const float* b_out    = (const float*)d_in[16];
    float* out = (float*)d_out;

    k_decoder<<<NBLK, 512>>>(inputs, hidden, enc, tindices,
                             W_attn, b_attn, v_attn,
                             Wi0, Wh0, bi0, bh0,
                             Wi1, Wh1, bi1, bh1,
                             W_out, b_out, out);
}

// round 9
// speedup vs baseline: 1.6841x; 1.0629x over previous
#include <cuda_runtime.h>
#include <cuda_bf16.h>
#include <math.h>

typedef unsigned int uint;
typedef __nv_bfloat16 bf16;

#define BB   64
#define DECL 12
#define FF   32
#define HH   512
#define EE   96
#define TT   4
#define G3   1536
#define NPRE 3584   /* 512 (query) + 1536 (gh0) + 1536 (gh1) */
#define KX0  544    /* F + H */
#define KOUT 1056   /* 2H + F */
#define NBLK 148
#define SRB  72     /* bf16 smem plane row stride (conflict-free) */

// ---------------- fp32 scratch ----------------
__device__ __align__(16) float g_encproj[BB*EE*HH];   // 12.6 MB
__device__ __align__(16) float g_h0[BB*HH];
__device__ __align__(16) float g_h1[BB*HH];
__device__ __align__(16) float g_cur[BB*FF];
__device__ __align__(16) float g_pre[4][BB*NPRE];     // K-split x4 partials: query|gh0|gh1
__device__ __align__(16) float g_gi[8][BB*G3];        // K-split x8 partials for gi
__device__ __align__(16) float g_ws[BB*HH];
__device__ __align__(16) float g_sc[BB*EE];           // attention scores

// ---------------- bf16 hi/lo planes (split once, reused) ----------------
__device__ __align__(16) bf16 gb_encH[BB*EE*HH], gb_encL[BB*EE*HH];
__device__ __align__(16) bf16 gb_WaeH[HH*HH],    gb_WaeL[HH*HH];
__device__ __align__(16) bf16 gb_WahH[HH*HH],    gb_WahL[HH*HH];
__device__ __align__(16) bf16 gb_Wh0H[G3*HH],    gb_Wh0L[G3*HH];
__device__ __align__(16) bf16 gb_Wh1H[G3*HH],    gb_Wh1L[G3*HH];
__device__ __align__(16) bf16 gb_Wi0H[G3*KX0],   gb_Wi0L[G3*KX0];
__device__ __align__(16) bf16 gb_Wi1H[G3*HH],    gb_Wi1L[G3*HH];
__device__ __align__(16) bf16 gb_h0H[BB*HH],     gb_h0L[BB*HH];
__device__ __align__(16) bf16 gb_h1H[BB*HH],     gb_h1L[BB*HH];
__device__ __align__(16) bf16 gb_x0H[BB*KX0],    gb_x0L[BB*KX0];

__device__ unsigned g_bar_cnt = 0;
__device__ unsigned g_bar_gen = 0;

// ---------------- shared ----------------
__shared__ __align__(16) bf16 sAH2[64*SRB];
__shared__ __align__(16) bf16 sAL2[64*SRB];
__shared__ __align__(16) bf16 sWH2[64*SRB];
__shared__ __align__(16) bf16 sWL2[64*SRB];
__shared__ __align__(16) float sBuf[1100];

// ---------------- helpers ----------------
__device__ __forceinline__ float fast_sigmoid(float x) {
    return 1.0f / (1.0f + __expf(-x));
}
__device__ __forceinline__ float fast_tanh(float x) {
    float e = __expf(-2.0f * fabsf(x));
    float t = (1.0f - e) / (1.0f + e);
    return copysignf(t, x);
}
__device__ __forceinline__ void split1(float x, bf16 &h, bf16 &l) {
    h = __float2bfloat16(x);
    l = __float2bfloat16(x - __bfloat162float(h));
}
__device__ __forceinline__ uint lds32b(const bf16* p, int r, int c) {
    return *reinterpret_cast<const uint*>(&p[r*SRB + c]);
}
__device__ __forceinline__ void mma16816(float* d, const uint* a, uint b0, uint b1) {
    asm volatile(
        "mma.sync.aligned.m16n8k16.row.col.f32.bf16.bf16.f32 "
        "{%0,%1,%2,%3},{%4,%5,%6,%7},{%8,%9},{%0,%1,%2,%3};"
        : "+f"(d[0]), "+f"(d[1]), "+f"(d[2]), "+f"(d[3])
        : "r"(a[0]), "r"(a[1]), "r"(a[2]), "r"(a[3]), "r"(b0), "r"(b1));
}

// grid barrier (proven)
__device__ __forceinline__ void gsync() {
    __syncthreads();
    if (threadIdx.x == 0) {
        __threadfence();
        unsigned gen = *((volatile unsigned*)&g_bar_gen);
        if (atomicAdd(&g_bar_cnt, 1u) == (unsigned)(NBLK - 1)) {
            g_bar_cnt = 0;
            __threadfence();
            *((volatile unsigned*)&g_bar_gen) = gen + 1u;
        } else {
            while (*((volatile unsigned*)&g_bar_gen) == gen) { }
        }
    }
    __syncthreads();
}

// ---------------- bf16x3 TC GEMM on pre-split planes ----------------
// C[64][64] = A[64][klen] @ W[64][klen]^T ; klen % 32 == 0, chunks of 64.
// ACG: activations (ldcg) vs init-written planes (ldg).
template<bool ACG>
__device__ __forceinline__ void gemm64b(
    const bf16* __restrict__ AH, const bf16* __restrict__ AL, int lda,
    const bf16* __restrict__ WH, const bf16* __restrict__ WL, int ldw,
    float* __restrict__ C, int ldc, int klen)
{
    const int tid  = threadIdx.x;
    const int warp = tid >> 5, lane = tid & 31;
    const int rt = warp >> 2, ct = warp & 3;
    const int g  = lane >> 2;
    const int q  = (lane & 3) << 1;
    const int srow = tid >> 3, scol = (tid & 7) << 3;   // 8 bf16 per thread
    float d[2][4] = {};

    for (int k0 = 0; k0 < klen; k0 += 64) {
        const int rem = klen - k0;          // 64 or 32 (tail)
        if (scol < rem) {
            const uint4* pah = reinterpret_cast<const uint4*>(&AH[srow*lda + k0 + scol]);
            const uint4* pal = reinterpret_cast<const uint4*>(&AL[srow*lda + k0 + scol]);
            const uint4* pwh = reinterpret_cast<const uint4*>(&WH[srow*ldw + k0 + scol]);
            const uint4* pwl = reinterpret_cast<const uint4*>(&WL[srow*ldw + k0 + scol]);
            uint4 vah = ACG ? __ldcg(pah) : __ldg(pah);
            uint4 val = ACG ? __ldcg(pal) : __ldg(pal);
            uint4 vwh = __ldg(pwh);
            uint4 vwl = __ldg(pwl);
            *reinterpret_cast<uint4*>(&sAH2[srow*SRB + scol]) = vah;
            *reinterpret_cast<uint4*>(&sAL2[srow*SRB + scol]) = val;
            *reinterpret_cast<uint4*>(&sWH2[srow*SRB + scol]) = vwh;
            *reinterpret_cast<uint4*>(&sWL2[srow*SRB + scol]) = vwl;
        }
        __syncthreads();

        #pragma unroll
        for (int ks = 0; ks < 64; ks += 16) {
            if (ks < rem) {
                uint aH[4], aL[4];
                const int r0 = rt*16 + g;
                aH[0] = lds32b(sAH2, r0,     ks+q);   aH[1] = lds32b(sAH2, r0 + 8, ks+q);
                aH[2] = lds32b(sAH2, r0,     ks+q+8); aH[3] = lds32b(sAH2, r0 + 8, ks+q+8);
                aL[0] = lds32b(sAL2, r0,     ks+q);   aL[1] = lds32b(sAL2, r0 + 8, ks+q);
                aL[2] = lds32b(sAL2, r0,     ks+q+8); aL[3] = lds32b(sAL2, r0 + 8, ks+q+8);
                #pragma unroll
                for (int nt = 0; nt < 2; nt++) {
                    const int n0 = ct*16 + nt*8 + g;
                    uint bH0 = lds32b(sWH2, n0, ks+q), bH1 = lds32b(sWH2, n0, ks+q+8);
                    uint bL0 = lds32b(sWL2, n0, ks+q), bL1 = lds32b(sWL2, n0, ks+q+8);
                    mma16816(d[nt], aH, bH0, bH1);   // hi*hi
                    mma16816(d[nt], aH, bL0, bL1);   // hi*lo
                    mma16816(d[nt], aL, bH0, bH1);   // lo*hi
                }
            }
        }
        __syncthreads();
    }

    const int r0 = rt*16 + g;
    #pragma unroll
    for (int nt = 0; nt < 2; nt++) {
        const int c0 = ct*16 + nt*8 + q;
        __stcg(reinterpret_cast<float2*>(&C[r0*ldc + c0]),       make_float2(d[nt][0], d[nt][1]));
        __stcg(reinterpret_cast<float2*>(&C[(r0 + 8)*ldc + c0]), make_float2(d[nt][2], d[nt][3]));
    }
}

// ---------------- the whole decoder, persistent ----------------
__global__ __launch_bounds__(512, 1) void k_decoder(
    const float* __restrict__ inputs, const float* __restrict__ hidden,
    const float* __restrict__ enc,    const int* __restrict__ tind,
    const float* __restrict__ Wattn,  const float* __restrict__ b_attn,
    const float* __restrict__ v_attn,
    const float* __restrict__ Wi0, const float* __restrict__ Wh0,
    const float* __restrict__ bi0, const float* __restrict__ bh0,
    const float* __restrict__ Wi1, const float* __restrict__ Wh1,
    const float* __restrict__ bi1, const float* __restrict__ bh1,
    const float* __restrict__ W_out, const float* __restrict__ b_out,
    float* __restrict__ dout)
{
    const int bid  = blockIdx.x;
    const int tid  = threadIdx.x;
    const int warp = tid >> 5, lane = tid & 31;
    const int gtid = bid*512 + tid;
    const int gstr = NBLK*512;

    // ===== init: copies + one-time bf16 splits =====
    for (int i = gtid; i < BB*HH; i += gstr) {
        float h0v = __ldg(&hidden[i]);
        float h1v = __ldg(&hidden[BB*HH + i]);
        __stcg(&g_h0[i], h0v);
        __stcg(&g_h1[i], h1v);
        bf16 hh, hl;
        split1(h0v, hh, hl); __stcg(&gb_h0H[i], hh); __stcg(&gb_h0L[i], hl);
        split1(h1v, hh, hl); __stcg(&gb_h1H[i], hh); __stcg(&gb_h1L[i], hl);
    }
    for (int i = gtid; i < BB*FF; i += gstr) {
        int b = i >> 5, f = i & 31;
        __stcg(&g_cur[i], __ldg(&inputs[b*DECL*FF + f]));
    }
    for (int i = gtid; i < BB*EE*HH; i += gstr) {
        bf16 h, l; split1(__ldg(&enc[i]), h, l);
        __stcg(&gb_encH[i], h); __stcg(&gb_encL[i], l);
    }
    for (int i = gtid; i < HH*HH; i += gstr) {
        int gg = i >> 9, k = i & 511;
        bf16 h, l;
        split1(__ldg(&Wattn[gg*(2*HH) + k]), h, l);
        __stcg(&gb_WahH[i], h); __stcg(&gb_WahL[i], l);
        split1(__ldg(&Wattn[gg*(2*HH) + HH + k]), h, l);
        __stcg(&gb_WaeH[i], h); __stcg(&gb_WaeL[i], l);
    }
    for (int i = gtid; i < G3*HH; i += gstr) {
        bf16 h, l;
        split1(__ldg(&Wh0[i]), h, l); __stcg(&gb_Wh0H[i], h); __stcg(&gb_Wh0L[i], l);
        split1(__ldg(&Wh1[i]), h, l); __stcg(&gb_Wh1H[i], h); __stcg(&gb_Wh1L[i], l);
        split1(__ldg(&Wi1[i]), h, l); __stcg(&gb_Wi1H[i], h); __stcg(&gb_Wi1L[i], l);
    }
    for (int i = gtid; i < G3*KX0; i += gstr) {
        bf16 h, l; split1(__ldg(&Wi0[i]), h, l);
        __stcg(&gb_Wi0H[i], h); __stcg(&gb_Wi0L[i], l);
    }
    gsync();

    // ===== phase E: enc_proj (96 M-tiles x 8 N-tiles, K=512) =====
    for (int it = bid; it < 96*8; it += NBLK) {
        int m = it >> 3, n = it & 7;
        gemm64b<false>(gb_encH + m*64*HH, gb_encL + m*64*HH, HH,
                       gb_WaeH + n*64*HH, gb_WaeL + n*64*HH, HH,
                       g_encproj + m*64*HH + n*64, HH, HH);
    }
    gsync();

    // ===== 12 decode steps =====
    for (int t = 0; t < DECL; t++) {
        // --- P1: pre GEMM (query|gh0|gh1): 56 N-tiles(64) x Ksplit4(128) = 224 jobs
        for (int it = bid; it < 224; it += NBLK) {
            int col0 = (it >> 2) * 64;
            int s    = it & 3;
            int k0   = s * 128;
            const bf16 *AH, *AL, *WH, *WL;
            if (col0 < 512) {
                AH = gb_h1H; AL = gb_h1L;
                WH = gb_WahH + col0*HH; WL = gb_WahL + col0*HH;
            } else if (col0 < 2048) {
                AH = gb_h0H; AL = gb_h0L;
                WH = gb_Wh0H + (col0-512)*HH; WL = gb_Wh0L + (col0-512)*HH;
            } else {
                AH = gb_h1H; AL = gb_h1L;
                WH = gb_Wh1H + (col0-2048)*HH; WL = gb_Wh1L + (col0-2048)*HH;
            }
            gemm64b<true>(AH + k0, AL + k0, HH, WH + k0, WL + k0, HH,
                          g_pre[s] + col0, NPRE, 128);
        }
        gsync();

        // --- P2: scores: job = (b, part), 16 energies; 384 jobs
        for (int it = bid; it < BB*6; it += NBLK) {
            __syncthreads();
            int b = it / 6, part = it % 6;
            float* qs = sBuf;
            float* vs = sBuf + 512;
            float qv = __ldg(&b_attn[tid]);
            #pragma unroll
            for (int s = 0; s < 4; s++) qv += __ldcg(&g_pre[s][b*NPRE + tid]);
            qs[tid] = qv;
            vs[tid] = __ldg(&v_attn[tid]);
            __syncthreads();
            int e = part*16 + warp;
            const float4* ep4 = reinterpret_cast<const float4*>(g_encproj + (b*EE + e)*HH);
            float ssum = 0.0f;
            #pragma unroll
            for (int i = 0; i < 4; i++) {
                float4 v = __ldcg(&ep4[i*32 + lane]);
                int gg = (i*32 + lane) * 4;
                ssum += fast_tanh(v.x + qs[gg  ]) * vs[gg  ];
                ssum += fast_tanh(v.y + qs[gg+1]) * vs[gg+1];
                ssum += fast_tanh(v.z + qs[gg+2]) * vs[gg+2];
                ssum += fast_tanh(v.w + qs[gg+3]) * vs[gg+3];
            }
            #pragma unroll
            for (int off = 16; off > 0; off >>= 1)
                ssum += __shfl_xor_sync(0xffffffffu, ssum, off);
            if (lane == 0) __stcg(&g_sc[b*EE + e], ssum);
        }
        gsync();

        // --- P3: softmax + ws + assemble x0 (fp32 ws + bf16 planes) : 64 jobs
        for (int it = bid; it < BB; it += NBLK) {
            __syncthreads();
            int b = it;
            float* sc = sBuf;
            if (warp == 0) {
                float s0 = __ldcg(&g_sc[b*EE + lane]);
                float s1 = __ldcg(&g_sc[b*EE + lane + 32]);
                float s2 = __ldcg(&g_sc[b*EE + lane + 64]);
                float m = fmaxf(s0, fmaxf(s1, s2));
                #pragma unroll
                for (int off = 16; off > 0; off >>= 1)
                    m = fmaxf(m, __shfl_xor_sync(0xffffffffu, m, off));
                float p0 = __expf(s0-m), p1 = __expf(s1-m), p2 = __expf(s2-m);
                float sum = p0 + p1 + p2;
                #pragma unroll
                for (int off = 16; off > 0; off >>= 1)
                    sum += __shfl_xor_sync(0xffffffffu, sum, off);
                float inv = 1.0f / sum;
                sc[lane] = p0*inv; sc[lane+32] = p1*inv; sc[lane+64] = p2*inv;
            }
            __syncthreads();
            float acc = 0.0f;
            const float* eb = enc + b*EE*HH + tid;
            #pragma unroll 8
            for (int e = 0; e < EE; e++) acc += sc[e] * __ldg(&eb[e*HH]);
            __stcg(&g_ws[b*HH + tid], acc);
            bf16 h, l; split1(acc, h, l);
            __stcg(&gb_x0H[b*KX0 + FF + tid], h);
            __stcg(&gb_x0L[b*KX0 + FF + tid], l);
            if (tid < FF) {
                float cv = __ldcg(&g_cur[b*FF + tid]);
                split1(cv, h, l);
                __stcg(&gb_x0H[b*KX0 + tid], h);
                __stcg(&gb_x0L[b*KX0 + tid], l);
            }
        }
        gsync();

        // --- P4: gi0 = x0 @ Wi0^T : 24 N-tiles(64) x Ksplit8 {96,64x7} = 192 jobs
        for (int it = bid; it < 192; it += NBLK) {
            int col0 = (it >> 3) * 64;
            int s    = it & 7;
            int k0   = (s == 0) ? 0 : (32 + s*64);
            int klen = (s == 0) ? 96 : 64;
            gemm64b<true>(gb_x0H + k0, gb_x0L + k0, KX0,
                          gb_Wi0H + col0*KX0 + k0, gb_Wi0L + col0*KX0 + k0, KX0,
                          g_gi[s] + col0, G3, klen);
        }
        gsync();

        // --- P5: GRU combine layer 0 -> h0 (fp32 + bf16 planes) : 64 jobs
        for (int it = bid; it < BB; it += NBLK) {
            int b = it, j = tid;
            float ir = __ldg(&bi0[j]), iz = __ldg(&bi0[j+HH]), in_ = __ldg(&bi0[j+2*HH]);
            float hr = __ldg(&bh0[j]), hz = __ldg(&bh0[j+HH]), hn  = __ldg(&bh0[j+2*HH]);
            #pragma unroll
            for (int s = 0; s < 8; s++) {
                const float* gi = g_gi[s] + b*G3;
                ir += __ldcg(&gi[j]); iz += __ldcg(&gi[j+HH]); in_ += __ldcg(&gi[j+2*HH]);
            }
            #pragma unroll
            for (int s = 0; s < 4; s++) {
                const float* gh = g_pre[s] + b*NPRE + 512;
                hr += __ldcg(&gh[j]); hz += __ldcg(&gh[j+HH]); hn += __ldcg(&gh[j+2*HH]);
            }
            float r = fast_sigmoid(ir + hr);
            float z = fast_sigmoid(iz + hz);
            float n = fast_tanh(in_ + r * hn);
            float hp = __ldcg(&g_h0[b*HH + j]);
            float h0n = (1.0f - z)*n + z*hp;
            __stcg(&g_h0[b*HH + j], h0n);
            bf16 h, l; split1(h0n, h, l);
            __stcg(&gb_h0H[b*HH + j], h);
            __stcg(&gb_h0L[b*HH + j], l);
        }
        gsync();

        // --- P6: gi1 = h0_new @ Wi1^T : 24 N-tiles(64) x Ksplit8(64) = 192 jobs
        for (int it = bid; it < 192; it += NBLK) {
            int col0 = (it >> 3) * 64;
            int s    = it & 7;
            int k0   = s * 64;
            gemm64b<true>(gb_h0H + k0, gb_h0L + k0, HH,
                          gb_Wi1H + col0*HH + k0, gb_Wi1L + col0*HH + k0, HH,
                          g_gi[s] + col0, G3, 64);
        }
        gsync();

        // --- P7: GRU combine layer 1 -> h1, fused out-proj + next cur : 64 jobs
        for (int it = bid; it < BB; it += NBLK) {
            __syncthreads();
            int b = it, j = tid;
            float* ho  = sBuf;          // 512
            float* red = sBuf + 512;    // 64 + 4
            float ir = __ldg(&bi1[j]), iz = __ldg(&bi1[j+HH]), in_ = __ldg(&bi1[j+2*HH]);
            float hr = __ldg(&bh1[j]), hz = __ldg(&bh1[j+HH]), hn  = __ldg(&bh1[j+2*HH]);
            #pragma unroll
            for (int s = 0; s < 8; s++) {
                const float* gi = g_gi[s] + b*G3;
                ir += __ldcg(&gi[j]); iz += __ldcg(&gi[j+HH]); in_ += __ldcg(&gi[j+2*HH]);
            }
            #pragma unroll
            for (int s = 0; s < 4; s++) {
                const float* gh = g_pre[s] + b*NPRE + 2048;
                hr += __ldcg(&gh[j]); hz += __ldcg(&gh[j+HH]); hn += __ldcg(&gh[j+2*HH]);
            }
            float r = fast_sigmoid(ir + hr);
            float z = fast_sigmoid(iz + hz);
            float n = fast_tanh(in_ + r * hn);
            float hp = __ldcg(&g_h1[b*HH + j]);
            float h1n = (1.0f - z)*n + z*hp;
            __stcg(&g_h1[b*HH + j], h1n);
            bf16 h, l; split1(h1n, h, l);
            __stcg(&gb_h1H[b*HH + j], h);
            __stcg(&gb_h1L[b*HH + j], l);
            ho[j] = h1n;
            __syncthreads();

            float a0 = 0.f, a1 = 0.f, a2 = 0.f, a3 = 0.f;
            for (int k = tid; k < KOUT; k += 512) {
                float x;
                if (k < HH)          x = ho[k];
                else if (k < 2*HH)   x = __ldcg(&g_ws[b*HH + k - HH]);
                else                 x = __ldcg(&g_cur[b*FF + (k - 2*HH)]);
                a0 += x * __ldg(&W_out[k]);
                a1 += x * __ldg(&W_out[KOUT + k]);
                a2 += x * __ldg(&W_out[2*KOUT + k]);
                a3 += x * __ldg(&W_out[3*KOUT + k]);
            }
            #pragma unroll
            for (int off = 16; off > 0; off >>= 1) {
                a0 += __shfl_xor_sync(0xffffffffu, a0, off);
                a1 += __shfl_xor_sync(0xffffffffu, a1, off);
                a2 += __shfl_xor_sync(0xffffffffu, a2, off);
                a3 += __shfl_xor_sync(0xffffffffu, a3, off);
            }
            if (lane == 0) {
                red[0*16 + warp] = a0; red[1*16 + warp] = a1;
                red[2*16 + warp] = a2; red[3*16 + warp] = a3;
            }
            __syncthreads();
            if (tid < 4) {
                float s = __ldg(&b_out[tid]);
                #pragma unroll
                for (int w = 0; w < 16; w++) s += red[tid*16 + w];
                dout[(b*DECL + t)*TT + tid] = s;
                red[64 + tid] = s;
            }
            __syncthreads();
            if (tid < FF)
                __stcg(&g_cur[b*FF + tid], __ldg(&inputs[(b*DECL + t)*FF + tid]));
            __syncthreads();
            if (tid < TT)
                __stcg(&g_cur[b*FF + __ldg(&tind[tid])], red[64 + tid]);
        }
        if (t < DECL - 1) gsync();
    }
}

// ---------------- launch ----------------
extern "C" void kernel_launch(void* const* d_in, const int* in_sizes, int n_in,
                              void* d_out, int out_size)
{
    const float* inputs   = (const float*)d_in[0];
    const float* hidden   = (const float*)d_in[1];
    const float* enc      = (const float*)d_in[2];
    const int*   tindices = (const int*)  d_in[3];
    const float* W_attn   = (const float*)d_in[4];
    const float* b_attn   = (const float*)d_in[5];
    const float* v_attn   = (const float*)d_in[6];
    const float* Wi0      = (const float*)d_in[7];
    const float* Wh0      = (const float*)d_in[8];
    const float* bi0      = (const float*)d_in[9];
    const float* bh0      = (const float*)d_in[10];
    const float* Wi1      = (const float*)d_in[11];
    const float* Wh1      = (const float*)d_in[12];
    const float* bi1      = (const float*)d_in[13];
    const float* bh1      = (const float*)d_in[14];
    const float* W_out    = (const float*)d_in[15];
    const float* b_out    = (const float*)d_in[16];
    float* out = (float*)d_out;

    k_decoder<<<NBLK, 512>>>(inputs, hidden, enc, tindices,
                             W_attn, b_attn, v_attn,
                             Wi0, Wh0, bi0, bh0,
                             Wi1, Wh1, bi1, bh1,
                             W_out, b_out, out);
}